// round 2
// baseline (speedup 1.0000x reference)
#include <cuda_runtime.h>
#include <math.h>

#define NB    4
#define NPTS  8192
#define CIN   32
#define COUT  64
#define KNN   32
#define NE    (NB*NPTS*KNN)      /* 1048576 edges */
#define EPB   (NPTS*KNN)         /* 262144 edges per batch */
#define BC    (NB*COUT)          /* 256 (batch,channel) pairs */
#define CNTF  ((float)EPB)
#define EPSV  1e-5f
#define SLOPE 0.1f

// 256 MB intermediate (float4 for guaranteed 16B alignment)
__device__ float4 g_Y[(size_t)NE * (COUT/4)];
__device__ float  g_sum[BC], g_sumsq[BC], g_s[BC], g_t[BC];

// ---------------------------------------------------------------- zero stats
__global__ void k_zero() {
    int i = threadIdx.x;
    g_sum[i] = 0.f; g_sumsq[i] = 0.f;
}

// ------------------------------------------- stage 1: gather + concat + GEMM1
__global__ void __launch_bounds__(256) k_stage1(
    const float* __restrict__ signal, const int* __restrict__ edges,
    const float* __restrict__ efeat,  const float* __restrict__ W1)
{
    __shared__ float sW[35*64];               // sW[c*64+o] = W1[o][c]
    for (int i = threadIdx.x; i < 35*64; i += 256) {
        int o = i / 35, c = i - o*35;
        sW[c*64 + o] = W1[i];
    }
    __syncthreads();

    int e = blockIdx.x * 256 + threadIdx.x;
    int idx = edges[e];
    const float4* src = (const float4*)signal + (size_t)idx * (CIN/4);

    float x[35];
    #pragma unroll
    for (int i = 0; i < CIN/4; i++) {
        float4 v = src[i];
        x[i*4+0]=v.x; x[i*4+1]=v.y; x[i*4+2]=v.z; x[i*4+3]=v.w;
    }
    x[32]=efeat[e*3+0]; x[33]=efeat[e*3+1]; x[34]=efeat[e*3+2];

    float4 acc[16];
    #pragma unroll
    for (int o = 0; o < 16; o++) acc[o] = make_float4(0.f,0.f,0.f,0.f);

    #pragma unroll
    for (int c = 0; c < 35; c++) {
        float xc = x[c];
        const float4* w4 = (const float4*)(sW + c*64);
        #pragma unroll
        for (int o = 0; o < 16; o++) {
            float4 w = w4[o];
            acc[o].x = fmaf(w.x, xc, acc[o].x);
            acc[o].y = fmaf(w.y, xc, acc[o].y);
            acc[o].z = fmaf(w.z, xc, acc[o].z);
            acc[o].w = fmaf(w.w, xc, acc[o].w);
        }
    }
    float4* dst = g_Y + (size_t)e * 16;
    #pragma unroll
    for (int o = 0; o < 16; o++) dst[o] = acc[o];
}

// ------------------------------------------------ per-(b,c) sum / sumsq of Y
__global__ void __launch_bounds__(256) k_stats() {
    int c4 = threadIdx.x & 15;      // which float4 of the 64 channels
    int eo = threadIdx.x >> 4;      // edge offset within chunk stride
    size_t base = (size_t)blockIdx.x * 1024;     // 1024 edges per block
    int b = (int)(base / EPB);                   // chunk never crosses a batch

    float4 s = make_float4(0.f,0.f,0.f,0.f), q = s;
    for (int i = eo; i < 1024; i += 16) {
        float4 v = g_Y[(base + i)*16 + c4];
        s.x += v.x; s.y += v.y; s.z += v.z; s.w += v.w;
        q.x = fmaf(v.x,v.x,q.x); q.y = fmaf(v.y,v.y,q.y);
        q.z = fmaf(v.z,v.z,q.z); q.w = fmaf(v.w,v.w,q.w);
    }
    __shared__ float4 shS[256], shQ[256];
    shS[threadIdx.x] = s; shQ[threadIdx.x] = q;
    __syncthreads();
    if (eo == 0) {
        for (int j = 1; j < 16; j++) {
            float4 a = shS[j*16 + c4];
            s.x+=a.x; s.y+=a.y; s.z+=a.z; s.w+=a.w;
            float4 bq = shQ[j*16 + c4];
            q.x+=bq.x; q.y+=bq.y; q.z+=bq.z; q.w+=bq.w;
        }
        int cb = b*COUT + c4*4;
        atomicAdd(&g_sum[cb+0], s.x); atomicAdd(&g_sum[cb+1], s.y);
        atomicAdd(&g_sum[cb+2], s.z); atomicAdd(&g_sum[cb+3], s.w);
        atomicAdd(&g_sumsq[cb+0], q.x); atomicAdd(&g_sumsq[cb+1], q.y);
        atomicAdd(&g_sumsq[cb+2], q.z); atomicAdd(&g_sumsq[cb+3], q.w);
    }
}

// ------------------------------------- stats -> (scale, shift), reset accum
__global__ void k_finalize(const float* __restrict__ gam, const float* __restrict__ bet) {
    int i = threadIdx.x;          // 256 = (b,c)
    float mean = g_sum[i]   * (1.f/CNTF);
    float var  = g_sumsq[i] * (1.f/CNTF) - mean*mean;
    float sc   = gam[i & 63] * rsqrtf(var + EPSV);
    g_s[i] = sc;
    g_t[i] = bet[i & 63] - mean * sc;
    g_sum[i] = 0.f; g_sumsq[i] = 0.f;
}

// --------------------- stages 2/3: norm + leaky + 64x64 GEMM (in-place on Y)
__global__ void __launch_bounds__(256) k_stage(const float* __restrict__ W) {
    __shared__ float sW[64*64];               // sW[c*64+o] = W[o][c]
    __shared__ float sS[64], sT[64];
    int b = blockIdx.x >> 10;                 // 1024 blocks per batch
    for (int i = threadIdx.x; i < 4096; i += 256) {
        int o = i >> 6, c = i & 63;
        sW[c*64 + o] = W[i];
    }
    if (threadIdx.x < 64) {
        sS[threadIdx.x] = g_s[b*64 + threadIdx.x];
        sT[threadIdx.x] = g_t[b*64 + threadIdx.x];
    }
    __syncthreads();

    size_t e = (size_t)blockIdx.x * 256 + threadIdx.x;
    float* row = (float*)(g_Y + e*16);

    float4 acc[16];
    #pragma unroll
    for (int o = 0; o < 16; o++) acc[o] = make_float4(0.f,0.f,0.f,0.f);

    for (int c = 0; c < 64; c++) {
        float xc = fmaf(row[c], sS[c], sT[c]);
        xc = (xc >= 0.f) ? xc : SLOPE * xc;
        const float4* w4 = (const float4*)(sW + c*64);
        #pragma unroll
        for (int o = 0; o < 16; o++) {
            float4 w = w4[o];
            acc[o].x = fmaf(w.x, xc, acc[o].x);
            acc[o].y = fmaf(w.y, xc, acc[o].y);
            acc[o].z = fmaf(w.z, xc, acc[o].z);
            acc[o].w = fmaf(w.w, xc, acc[o].w);
        }
    }
    float4* dst = (float4*)row;
    #pragma unroll
    for (int o = 0; o < 16; o++) dst[o] = acc[o];
}

// -------------------------- final: norm3 + leaky + max over K + (B,N,C) store
__global__ void __launch_bounds__(256) k_out(float* __restrict__ out) {
    int tid = blockIdx.x * 256 + threadIdx.x;   // covers (B*N)*16
    int c4 = tid & 15;
    int r  = tid >> 4;                           // row = b*N + n
    int b  = r >> 13;                            // N = 8192
    float4 sc = ((const float4*)g_s)[b*16 + c4];
    float4 tt = ((const float4*)g_t)[b*16 + c4];
    float4 m = make_float4(-3.4e38f,-3.4e38f,-3.4e38f,-3.4e38f);
    size_t base = (size_t)r * KNN;
    for (int kk = 0; kk < KNN; kk++) {
        float4 v = g_Y[(base + kk)*16 + c4];
        float y;
        y = fmaf(v.x, sc.x, tt.x); y = (y>=0.f)?y:SLOPE*y; m.x = fmaxf(m.x, y);
        y = fmaf(v.y, sc.y, tt.y); y = (y>=0.f)?y:SLOPE*y; m.y = fmaxf(m.y, y);
        y = fmaf(v.z, sc.z, tt.z); y = (y>=0.f)?y:SLOPE*y; m.z = fmaxf(m.z, y);
        y = fmaf(v.w, sc.w, tt.w); y = (y>=0.f)?y:SLOPE*y; m.w = fmaxf(m.w, y);
    }
    ((float4*)out)[(size_t)r*16 + c4] = m;
}

// ---------------------------------------------------------------------------
extern "C" void kernel_launch(void* const* d_in, const int* in_sizes, int n_in,
                              void* d_out, int out_size)
{
    const float* signal = (const float*)d_in[0];
    const int*   edges  = (const int*)d_in[1];
    const float* efeat  = (const float*)d_in[2];
    // d_in[3] = k (constant 32, baked in)
    const float* W1 = (const float*)d_in[4];
    const float* g1 = (const float*)d_in[5];
    const float* b1 = (const float*)d_in[6];
    const float* W2 = (const float*)d_in[7];
    const float* g2 = (const float*)d_in[8];
    const float* b2 = (const float*)d_in[9];
    const float* W3 = (const float*)d_in[10];
    const float* g3 = (const float*)d_in[11];
    const float* b3 = (const float*)d_in[12];
    float* out = (float*)d_out;

    k_zero<<<1, 256>>>();
    k_stage1<<<NE/256, 256>>>(signal, edges, efeat, W1);
    k_stats<<<NE/1024, 256>>>();
    k_finalize<<<1, 256>>>(g1, b1);
    k_stage<<<NE/256, 256>>>(W2);
    k_stats<<<NE/1024, 256>>>();
    k_finalize<<<1, 256>>>(g2, b2);
    k_stage<<<NE/256, 256>>>(W3);
    k_stats<<<NE/1024, 256>>>();
    k_finalize<<<1, 256>>>(g3, b3);
    k_out<<<(NB*NPTS*16)/256, 256>>>(out);
}

// round 3
// speedup vs baseline: 1.3929x; 1.3929x over previous
#include <cuda_runtime.h>
#include <math.h>

#define NB    4
#define NPTS  8192
#define CIN   32
#define COUT  64
#define KNN   32
#define NE    (NB*NPTS*KNN)      /* 1048576 edges */
#define EPB   (NPTS*KNN)         /* 262144 edges per batch */
#define BC    (NB*COUT)          /* 256 (batch,channel) pairs */
#define CNTF  ((float)EPB)
#define EPSV  1e-5f
#define SLOPE 0.1f

// 256 MB intermediate, SoA by channel-quad: plane c4 (0..15) holds float4 for
// channels [4*c4, 4*c4+4) of every edge. Index: c4*NE + e  -> fully coalesced.
__device__ float4 g_Y[(size_t)16 * NE];
__device__ float  g_sum[BC], g_sumsq[BC], g_s[BC], g_t[BC];

// ---------------------------------------------------------------- zero stats
__global__ void k_zero() {
    int i = threadIdx.x;
    g_sum[i] = 0.f; g_sumsq[i] = 0.f;
}

// ------------------------------------------- stage 1: gather + concat + GEMM1
__global__ void __launch_bounds__(256) k_stage1(
    const float* __restrict__ signal, const int* __restrict__ edges,
    const float* __restrict__ efeat,  const float* __restrict__ W1)
{
    __shared__ float sW[35*64];               // sW[c*64+o] = W1[o][c]
    for (int i = threadIdx.x; i < 35*64; i += 256) {
        int o = i / 35, c = i - o*35;
        sW[c*64 + o] = W1[i];
    }
    __syncthreads();

    int e = blockIdx.x * 256 + threadIdx.x;
    int idx = edges[e];
    const float4* src = (const float4*)signal + (size_t)idx * (CIN/4);

    float x[35];
    #pragma unroll
    for (int i = 0; i < CIN/4; i++) {
        float4 v = src[i];
        x[i*4+0]=v.x; x[i*4+1]=v.y; x[i*4+2]=v.z; x[i*4+3]=v.w;
    }
    x[32]=efeat[e*3+0]; x[33]=efeat[e*3+1]; x[34]=efeat[e*3+2];

    float4 acc[16];
    #pragma unroll
    for (int o = 0; o < 16; o++) acc[o] = make_float4(0.f,0.f,0.f,0.f);

    #pragma unroll
    for (int c = 0; c < 35; c++) {
        float xc = x[c];
        const float4* w4 = (const float4*)(sW + c*64);
        #pragma unroll
        for (int o = 0; o < 16; o++) {
            float4 w = w4[o];
            acc[o].x = fmaf(w.x, xc, acc[o].x);
            acc[o].y = fmaf(w.y, xc, acc[o].y);
            acc[o].z = fmaf(w.z, xc, acc[o].z);
            acc[o].w = fmaf(w.w, xc, acc[o].w);
        }
    }
    #pragma unroll
    for (int o = 0; o < 16; o++) g_Y[(size_t)o*NE + e] = acc[o];
}

// ---------------- per-(b,c) sum / sumsq of Y  (plane-parallel, coalesced)
// grid: b (2 bits) x c4 (4 bits) x chunk (6 bits) ; chunk = 4096 edges
__global__ void __launch_bounds__(256) k_stats() {
    int chunk = blockIdx.x & 63;
    int c4    = (blockIdx.x >> 6) & 15;
    int b     = blockIdx.x >> 10;
    size_t base = (size_t)c4 * NE + (size_t)b * EPB + (size_t)chunk * 4096;

    float4 s = make_float4(0.f,0.f,0.f,0.f), q = s;
    #pragma unroll
    for (int i = 0; i < 16; i++) {
        float4 v = g_Y[base + threadIdx.x + i*256];
        s.x += v.x; s.y += v.y; s.z += v.z; s.w += v.w;
        q.x = fmaf(v.x,v.x,q.x); q.y = fmaf(v.y,v.y,q.y);
        q.z = fmaf(v.z,v.z,q.z); q.w = fmaf(v.w,v.w,q.w);
    }
    __shared__ float4 shS[256], shQ[256];
    shS[threadIdx.x] = s; shQ[threadIdx.x] = q;
    __syncthreads();
    for (int off = 128; off > 0; off >>= 1) {
        if (threadIdx.x < off) {
            float4 a = shS[threadIdx.x + off];
            float4 bb = shQ[threadIdx.x + off];
            s.x+=a.x; s.y+=a.y; s.z+=a.z; s.w+=a.w;
            q.x+=bb.x; q.y+=bb.y; q.z+=bb.z; q.w+=bb.w;
            shS[threadIdx.x] = s; shQ[threadIdx.x] = q;
        }
        __syncthreads();
    }
    if (threadIdx.x == 0) {
        int cb = b*COUT + c4*4;
        atomicAdd(&g_sum[cb+0], s.x); atomicAdd(&g_sum[cb+1], s.y);
        atomicAdd(&g_sum[cb+2], s.z); atomicAdd(&g_sum[cb+3], s.w);
        atomicAdd(&g_sumsq[cb+0], q.x); atomicAdd(&g_sumsq[cb+1], q.y);
        atomicAdd(&g_sumsq[cb+2], q.z); atomicAdd(&g_sumsq[cb+3], q.w);
    }
}

// ------------------------------------- stats -> (scale, shift), reset accum
__global__ void k_finalize(const float* __restrict__ gam, const float* __restrict__ bet) {
    int i = threadIdx.x;          // 256 = (b,c)
    float mean = g_sum[i]   * (1.f/CNTF);
    float var  = g_sumsq[i] * (1.f/CNTF) - mean*mean;
    float sc   = gam[i & 63] * rsqrtf(var + EPSV);
    g_s[i] = sc;
    g_t[i] = bet[i & 63] - mean * sc;
    g_sum[i] = 0.f; g_sumsq[i] = 0.f;
}

// --------------------- stages 2/3: norm + leaky + 64x64 GEMM (in-place on Y)
__global__ void __launch_bounds__(256) k_stage(const float* __restrict__ W) {
    __shared__ float sW[64*64];               // sW[c*64+o] = W[o][c]
    __shared__ float sS[64], sT[64];
    int b = blockIdx.x >> 10;                 // 1024 blocks per batch
    for (int i = threadIdx.x; i < 4096; i += 256) {
        int o = i >> 6, c = i & 63;
        sW[c*64 + o] = W[i];
    }
    if (threadIdx.x < 64) {
        sS[threadIdx.x] = g_s[b*64 + threadIdx.x];
        sT[threadIdx.x] = g_t[b*64 + threadIdx.x];
    }
    __syncthreads();

    size_t e = (size_t)blockIdx.x * 256 + threadIdx.x;

    // load full row (coalesced across warp), apply norm + leaky
    float x[64];
    #pragma unroll
    for (int c4 = 0; c4 < 16; c4++) {
        float4 v = g_Y[(size_t)c4*NE + e];
        float y;
        y = fmaf(v.x, sS[c4*4+0], sT[c4*4+0]); x[c4*4+0] = (y>=0.f)?y:SLOPE*y;
        y = fmaf(v.y, sS[c4*4+1], sT[c4*4+1]); x[c4*4+1] = (y>=0.f)?y:SLOPE*y;
        y = fmaf(v.z, sS[c4*4+2], sT[c4*4+2]); x[c4*4+2] = (y>=0.f)?y:SLOPE*y;
        y = fmaf(v.w, sS[c4*4+3], sT[c4*4+3]); x[c4*4+3] = (y>=0.f)?y:SLOPE*y;
    }

    float4 acc[16];
    #pragma unroll
    for (int o = 0; o < 16; o++) acc[o] = make_float4(0.f,0.f,0.f,0.f);

    #pragma unroll 4
    for (int c = 0; c < 64; c++) {
        float xc = x[c];
        const float4* w4 = (const float4*)(sW + c*64);
        #pragma unroll
        for (int o = 0; o < 16; o++) {
            float4 w = w4[o];
            acc[o].x = fmaf(w.x, xc, acc[o].x);
            acc[o].y = fmaf(w.y, xc, acc[o].y);
            acc[o].z = fmaf(w.z, xc, acc[o].z);
            acc[o].w = fmaf(w.w, xc, acc[o].w);
        }
    }
    #pragma unroll
    for (int o = 0; o < 16; o++) g_Y[(size_t)o*NE + e] = acc[o];
}

// -------------------------- final: norm3 + leaky + max over K + (B,N,C) store
__global__ void __launch_bounds__(256) k_out(float* __restrict__ out) {
    int tid = blockIdx.x * 256 + threadIdx.x;   // covers (B*N)*16
    int c4 = tid & 15;
    int r  = tid >> 4;                           // row = b*N + n
    int b  = r >> 13;                            // N = 8192
    float4 sc = ((const float4*)g_s)[b*16 + c4];
    float4 tt = ((const float4*)g_t)[b*16 + c4];
    float4 m = make_float4(-3.4e38f,-3.4e38f,-3.4e38f,-3.4e38f);
    size_t base = (size_t)c4 * NE + (size_t)r * KNN;
    #pragma unroll 8
    for (int kk = 0; kk < KNN; kk++) {
        float4 v = g_Y[base + kk];
        float y;
        y = fmaf(v.x, sc.x, tt.x); y = (y>=0.f)?y:SLOPE*y; m.x = fmaxf(m.x, y);
        y = fmaf(v.y, sc.y, tt.y); y = (y>=0.f)?y:SLOPE*y; m.y = fmaxf(m.y, y);
        y = fmaf(v.z, sc.z, tt.z); y = (y>=0.f)?y:SLOPE*y; m.z = fmaxf(m.z, y);
        y = fmaf(v.w, sc.w, tt.w); y = (y>=0.f)?y:SLOPE*y; m.w = fmaxf(m.w, y);
    }
    ((float4*)out)[(size_t)r*16 + c4] = m;
}

// ---------------------------------------------------------------------------
extern "C" void kernel_launch(void* const* d_in, const int* in_sizes, int n_in,
                              void* d_out, int out_size)
{
    const float* signal = (const float*)d_in[0];
    const int*   edges  = (const int*)d_in[1];
    const float* efeat  = (const float*)d_in[2];
    // d_in[3] = k (constant 32, baked in)
    const float* W1 = (const float*)d_in[4];
    const float* g1 = (const float*)d_in[5];
    const float* b1 = (const float*)d_in[6];
    const float* W2 = (const float*)d_in[7];
    const float* g2 = (const float*)d_in[8];
    const float* b2 = (const float*)d_in[9];
    const float* W3 = (const float*)d_in[10];
    const float* g3 = (const float*)d_in[11];
    const float* b3 = (const float*)d_in[12];
    float* out = (float*)d_out;

    k_zero<<<1, 256>>>();
    k_stage1<<<NE/256, 256>>>(signal, edges, efeat, W1);
    k_stats<<<4096, 256>>>();
    k_finalize<<<1, 256>>>(g1, b1);
    k_stage<<<NE/256, 256>>>(W2);
    k_stats<<<4096, 256>>>();
    k_finalize<<<1, 256>>>(g2, b2);
    k_stage<<<NE/256, 256>>>(W3);
    k_stats<<<4096, 256>>>();
    k_finalize<<<1, 256>>>(g3, b3);
    k_out<<<(NB*NPTS*16)/256, 256>>>(out);
}